// round 7
// baseline (speedup 1.0000x reference)
#include <cuda_runtime.h>
#include <math_constants.h>

#define CC 192
#define KK 64
#define NBINS 2048
#define BIN_LO (-10.5f)
#define BIN_W  (21.0f / (float)NBINS)
#define BIN_INV ((float)NBINS / 21.0f)
// 2^23 + (-BIN_LO)*BIN_INV = 8388608 + 1024  (round-to-nearest bin; +-1 bin slack covers it)
#define BIN_MAGIC 8389632.0f
#define XCLAMP 10.49f
#define LIK_BOUND 1e-9f

// {y, lik} per (channel, code)
__device__ float2 g_tab[CC * KK];
// midpoints (63 real + 1 INF sentinel)
__device__ float g_mid[KK];
// per-bin descriptor: low byte = klo (#mids < binLeft(bin-1)), high bits = n (#mids in window)
__device__ unsigned int g_desc[NBINS];

__device__ __forceinline__ float softplusf(float x) {
    return fmaxf(x, 0.0f) + log1pf(expf(-fabsf(x)));
}

__device__ __forceinline__ int count_mids_below(const float* __restrict__ cb, float v) {
    int lo = 0, hi = KK - 1;   // lower_bound over 63 midpoints
    while (lo < hi) {
        int m = (lo + hi) >> 1;
        float mid = 0.5f * (cb[m] + cb[m + 1]);
        if (mid < v) lo = m + 1; else hi = m;
    }
    return lo;
}

// grid = 200 blocks x 128 threads.
// blocks [0,192): one channel each; tid<64 -> lower eval, tid>=64 -> upper eval.
// blocks [192,200): descriptor table (256 bins each) + midpoints (block 192).
__global__ void __launch_bounds__(128) build_lut_kernel(
    const float* __restrict__ cb,
    const float* __restrict__ m0, const float* __restrict__ m1,
    const float* __restrict__ m2, const float* __restrict__ m3,
    const float* __restrict__ m4,
    const float* __restrict__ b0, const float* __restrict__ b1,
    const float* __restrict__ b2, const float* __restrict__ b3,
    const float* __restrict__ b4,
    const float* __restrict__ f0, const float* __restrict__ f1,
    const float* __restrict__ f2, const float* __restrict__ f3)
{
    int tid = threadIdx.x;
    int blk = blockIdx.x;

    if (blk >= CC) {
        // ---- descriptor table + midpoints ----
        int bb = blk - CC;
        if (bb == 0 && tid < KK) {
            g_mid[tid] = (tid < KK - 1) ? 0.5f * (cb[tid] + cb[tid + 1]) : CUDART_INF_F;
        }
        #pragma unroll
        for (int r = 0; r < 2; r++) {
            int t = bb * 256 + r * 128 + tid;
            // safety window: [binLeft(t-1), binLeft(t+2))
            float wlo = BIN_LO + (float)(t - 1) * BIN_W;
            float whi = BIN_LO + (float)(t + 2) * BIN_W;
            int klo = count_mids_below(cb, wlo);
            int n   = count_mids_below(cb, whi) - klo;
            g_desc[t] = (unsigned)klo | ((unsigned)n << 8);
        }
    } else {
        int c = blk;
        int s = tid >> 6;      // 0 = lower, 1 = upper
        int k = tid & 63;

        float w0[3], w4[3], bb0[3], bb1[3], bb2[3], bb3[3], bb4;
        float t0[3], t1[3], t2[3], t3[3];
        float w1[9], w2[9], w3[9];
        #pragma unroll
        for (int j = 0; j < 3; j++) {
            w0[j]  = softplusf(m0[c * 3 + j]);
            w4[j]  = softplusf(m4[c * 3 + j]);
            bb0[j] = b0[c * 3 + j];
            bb1[j] = b1[c * 3 + j];
            bb2[j] = b2[c * 3 + j];
            bb3[j] = b3[c * 3 + j];
            t0[j]  = tanhf(f0[c * 3 + j]);
            t1[j]  = tanhf(f1[c * 3 + j]);
            t2[j]  = tanhf(f2[c * 3 + j]);
            t3[j]  = tanhf(f3[c * 3 + j]);
        }
        #pragma unroll
        for (int j = 0; j < 9; j++) {
            w1[j] = softplusf(m1[c * 9 + j]);
            w2[j] = softplusf(m2[c * 9 + j]);
            w3[j] = softplusf(m3[c * 9 + j]);
        }
        bb4 = b4[c];

        float u = cb[k] + (s ? 0.5f : -0.5f);
        float h[3], nt[3];
        #pragma unroll
        for (int j = 0; j < 3; j++) {
            h[j] = w0[j] * u + bb0[j];
            h[j] += t0[j] * tanhf(h[j]);
        }
        #pragma unroll
        for (int j = 0; j < 3; j++) {
            nt[j] = w1[j*3+0]*h[0] + w1[j*3+1]*h[1] + w1[j*3+2]*h[2] + bb1[j];
            nt[j] += t1[j] * tanhf(nt[j]);
        }
        #pragma unroll
        for (int j = 0; j < 3; j++) h[j] = nt[j];
        #pragma unroll
        for (int j = 0; j < 3; j++) {
            nt[j] = w2[j*3+0]*h[0] + w2[j*3+1]*h[1] + w2[j*3+2]*h[2] + bb2[j];
            nt[j] += t2[j] * tanhf(nt[j]);
        }
        #pragma unroll
        for (int j = 0; j < 3; j++) h[j] = nt[j];
        #pragma unroll
        for (int j = 0; j < 3; j++) {
            nt[j] = w3[j*3+0]*h[0] + w3[j*3+1]*h[1] + w3[j*3+2]*h[2] + bb3[j];
            nt[j] += t3[j] * tanhf(nt[j]);
        }
        #pragma unroll
        for (int j = 0; j < 3; j++) h[j] = nt[j];
        float out = w4[0]*h[0] + w4[1]*h[1] + w4[2]*h[2] + bb4;

        __shared__ float souts[2][KK];
        souts[s][k] = out;
        __syncthreads();

        if (tid < KK) {
            float lo = souts[0][tid], up = souts[1][tid];
            float ssum = lo + up;
            float sg = (ssum > 0.0f) ? -1.0f : ((ssum < 0.0f) ? 1.0f : 0.0f);
            float su = 1.0f / (1.0f + expf(-sg * up));
            float sl = 1.0f / (1.0f + expf(-sg * lo));
            float lik = fmaxf(fabsf(su - sl), LIK_BOUND);
            g_tab[c * KK + tid] = make_float2(cb[tid], lik);
        }
    }

    // PDL: allow the dependent (quant) kernel to begin launching
    asm volatile("griddepcontrol.launch_dependents;");
}

// Each block = 256 threads x 4 float4 = 4096 elements = exactly one (n,c) plane.
__global__ void __launch_bounds__(256) quant_lik_kernel(
    const float4* __restrict__ x4,
    float4* __restrict__ y4,
    float4* __restrict__ l4)
{
    __shared__ float4 sbin[NBINS];   // {y_lo, lik_lo (sign=flag), y_hi, lik_hi}
    __shared__ float2 stab[KK];
    __shared__ float  smid[KK];

    int tid = threadIdx.x;
    int c = blockIdx.x % CC;

    long base = (long)blockIdx.x * 1024 + tid;  // float4 units; stride 256

    // Prefetch x before waiting on the producer kernel (PDL overlap)
    float4 xv[4];
    #pragma unroll
    for (int v = 0; v < 4; v++) xv[v] = __ldcs(&x4[base + v * 256]);

    asm volatile("griddepcontrol.wait;" ::: "memory");

    if (tid < KK) {
        stab[tid] = g_tab[c * KK + tid];
        smid[tid] = g_mid[tid];
    }
    __syncthreads();

    // Build the fused per-channel bin table (8 entries/thread)
    #pragma unroll
    for (int r = 0; r < 8; r++) {
        int bin = tid + r * 256;
        unsigned d = g_desc[bin];
        int klo = (int)(d & 0xFFu);
        int n   = (int)(d >> 8);
        float2 lo2 = stab[klo];
        float2 hi2 = stab[min(klo + (n > 0 ? 1 : 0), KK - 1)];
        float flag_or_lik = (n >= 2) ? -(float)(klo + 1) : lo2.y;
        sbin[bin] = make_float4(lo2.x, flag_or_lik, hi2.x, hi2.y);
    }
    __syncthreads();

    const float* xs = (const float*)xv;

    #pragma unroll
    for (int v = 0; v < 4; v++) {
        float ys[4], ls[4];
        #pragma unroll
        for (int j = 0; j < 4; j++) {
            float xx = xs[v * 4 + j];
            float xc = fminf(fmaxf(xx, -XCLAMP), XCLAMP);
            int bin = __float_as_int(fmaf(xc, BIN_INV, BIN_MAGIC)) & 0x7FF;
            float4 e = sbin[bin];
            if (e.y < 0.0f) {
                // rare (~0.3%): >=2 midpoints in the window; exact scan
                int k = (int)(-e.y) - 1;
                while (smid[k] < xx) k++;   // smid[63] = +INF bounds
                float2 g = stab[k];
                ys[j] = g.x; ls[j] = g.y;
            } else {
                float thr = 0.5f * (e.x + e.z);   // == smid[klo] bit-exactly
                bool hi = thr < xx;
                ys[j] = hi ? e.z : e.x;
                ls[j] = hi ? e.w : e.y;
            }
        }
        long i = base + v * 256;
        __stcs(&y4[i], make_float4(ys[0], ys[1], ys[2], ys[3]));
        __stcs(&l4[i], make_float4(ls[0], ls[1], ls[2], ls[3]));
    }
}

extern "C" void kernel_launch(void* const* d_in, const int* in_sizes, int n_in,
                              void* d_out, int out_size)
{
    // metadata order: x, codebook, m0, b0, f0, m1, b1, f1, m2, b2, f2, m3, b3, f3, m4, b4
    const float* x  = (const float*)d_in[0];
    const float* cb = (const float*)d_in[1];
    const float* m0 = (const float*)d_in[2];
    const float* b0 = (const float*)d_in[3];
    const float* f0 = (const float*)d_in[4];
    const float* m1 = (const float*)d_in[5];
    const float* b1 = (const float*)d_in[6];
    const float* f1 = (const float*)d_in[7];
    const float* m2 = (const float*)d_in[8];
    const float* b2 = (const float*)d_in[9];
    const float* f2 = (const float*)d_in[10];
    const float* m3 = (const float*)d_in[11];
    const float* b3 = (const float*)d_in[12];
    const float* f3 = (const float*)d_in[13];
    const float* m4 = (const float*)d_in[14];
    const float* b4 = (const float*)d_in[15];

    long total = (long)in_sizes[0];        // 16*192*64*64 = 12582912
    int nblocks = (int)(total / 4096);     // one (n,c) plane per block

    float* yhat = (float*)d_out;
    float* lik  = (float*)d_out + total;

    build_lut_kernel<<<CC + NBINS / 256, 128>>>(
        cb, m0, m1, m2, m3, m4, b0, b1, b2, b3, b4, f0, f1, f2, f3);

    // Launch quant with Programmatic Stream Serialization (PDL overlap)
    cudaLaunchConfig_t cfg = {};
    cfg.gridDim = dim3((unsigned)nblocks);
    cfg.blockDim = dim3(256);
    cfg.dynamicSmemBytes = 0;
    cfg.stream = 0;
    cudaLaunchAttribute attrs[1];
    attrs[0].id = cudaLaunchAttributeProgrammaticStreamSerialization;
    attrs[0].val.programmaticStreamSerializationAllowed = 1;
    cfg.attrs = attrs;
    cfg.numAttrs = 1;
    cudaLaunchKernelEx(&cfg, quant_lik_kernel,
                       (const float4*)x, (float4*)yhat, (float4*)lik);
}

// round 8
// speedup vs baseline: 1.0085x; 1.0085x over previous
#include <cuda_runtime.h>
#include <math_constants.h>

#define CC 192
#define KK 64
#define NBINS 2048
#define BIN_LO (-10.5f)
#define BIN_W  (21.0f / (float)NBINS)
#define BIN_INV ((float)NBINS / 21.0f)
// 2^23 + (-BIN_LO)*BIN_INV = 8388608 + 1024  (round-to-nearest bin; +-1 bin slack covers it)
#define BIN_MAGIC 8389632.0f
#define XCLAMP 10.49f
#define LIK_BOUND 1e-9f
#define PLANES_PER_BLOCK 2

// {y, lik} per (channel, code)
__device__ float2 g_tab[CC * KK];
// midpoints (63 real + 1 INF sentinel)
__device__ float g_mid[KK];
// per-bin descriptor: low byte = klo (#mids < binLeft(bin-1)), high bits = n (#mids in window)
__device__ unsigned int g_desc[NBINS];

__device__ __forceinline__ float softplusf(float x) {
    return fmaxf(x, 0.0f) + log1pf(expf(-fabsf(x)));
}

__device__ __forceinline__ int count_mids_below(const float* __restrict__ cb, float v) {
    int lo = 0, hi = KK - 1;   // lower_bound over 63 midpoints
    while (lo < hi) {
        int m = (lo + hi) >> 1;
        float mid = 0.5f * (cb[m] + cb[m + 1]);
        if (mid < v) lo = m + 1; else hi = m;
    }
    return lo;
}

// grid = 200 blocks x 128 threads.
// blocks [0,192): one channel each; tid<64 -> lower eval, tid>=64 -> upper eval.
// blocks [192,200): descriptor table (256 bins each) + midpoints (block 192).
__global__ void __launch_bounds__(128) build_lut_kernel(
    const float* __restrict__ cb,
    const float* __restrict__ m0, const float* __restrict__ m1,
    const float* __restrict__ m2, const float* __restrict__ m3,
    const float* __restrict__ m4,
    const float* __restrict__ b0, const float* __restrict__ b1,
    const float* __restrict__ b2, const float* __restrict__ b3,
    const float* __restrict__ b4,
    const float* __restrict__ f0, const float* __restrict__ f1,
    const float* __restrict__ f2, const float* __restrict__ f3)
{
    int tid = threadIdx.x;
    int blk = blockIdx.x;

    if (blk >= CC) {
        int bb = blk - CC;
        if (bb == 0 && tid < KK) {
            g_mid[tid] = (tid < KK - 1) ? 0.5f * (cb[tid] + cb[tid + 1]) : CUDART_INF_F;
        }
        #pragma unroll
        for (int r = 0; r < 2; r++) {
            int t = bb * 256 + r * 128 + tid;
            // safety window: [binLeft(t-1), binLeft(t+2))
            float wlo = BIN_LO + (float)(t - 1) * BIN_W;
            float whi = BIN_LO + (float)(t + 2) * BIN_W;
            int klo = count_mids_below(cb, wlo);
            int n   = count_mids_below(cb, whi) - klo;
            g_desc[t] = (unsigned)klo | ((unsigned)n << 8);
        }
    } else {
        int c = blk;
        int s = tid >> 6;      // 0 = lower, 1 = upper
        int k = tid & 63;

        float w0[3], w4[3], bb0[3], bb1[3], bb2[3], bb3[3], bb4;
        float t0[3], t1[3], t2[3], t3[3];
        float w1[9], w2[9], w3[9];
        #pragma unroll
        for (int j = 0; j < 3; j++) {
            w0[j]  = softplusf(m0[c * 3 + j]);
            w4[j]  = softplusf(m4[c * 3 + j]);
            bb0[j] = b0[c * 3 + j];
            bb1[j] = b1[c * 3 + j];
            bb2[j] = b2[c * 3 + j];
            bb3[j] = b3[c * 3 + j];
            t0[j]  = tanhf(f0[c * 3 + j]);
            t1[j]  = tanhf(f1[c * 3 + j]);
            t2[j]  = tanhf(f2[c * 3 + j]);
            t3[j]  = tanhf(f3[c * 3 + j]);
        }
        #pragma unroll
        for (int j = 0; j < 9; j++) {
            w1[j] = softplusf(m1[c * 9 + j]);
            w2[j] = softplusf(m2[c * 9 + j]);
            w3[j] = softplusf(m3[c * 9 + j]);
        }
        bb4 = b4[c];

        float u = cb[k] + (s ? 0.5f : -0.5f);
        float h[3], nt[3];
        #pragma unroll
        for (int j = 0; j < 3; j++) {
            h[j] = w0[j] * u + bb0[j];
            h[j] += t0[j] * tanhf(h[j]);
        }
        #pragma unroll
        for (int j = 0; j < 3; j++) {
            nt[j] = w1[j*3+0]*h[0] + w1[j*3+1]*h[1] + w1[j*3+2]*h[2] + bb1[j];
            nt[j] += t1[j] * tanhf(nt[j]);
        }
        #pragma unroll
        for (int j = 0; j < 3; j++) h[j] = nt[j];
        #pragma unroll
        for (int j = 0; j < 3; j++) {
            nt[j] = w2[j*3+0]*h[0] + w2[j*3+1]*h[1] + w2[j*3+2]*h[2] + bb2[j];
            nt[j] += t2[j] * tanhf(nt[j]);
        }
        #pragma unroll
        for (int j = 0; j < 3; j++) h[j] = nt[j];
        #pragma unroll
        for (int j = 0; j < 3; j++) {
            nt[j] = w3[j*3+0]*h[0] + w3[j*3+1]*h[1] + w3[j*3+2]*h[2] + bb3[j];
            nt[j] += t3[j] * tanhf(nt[j]);
        }
        #pragma unroll
        for (int j = 0; j < 3; j++) h[j] = nt[j];
        float out = w4[0]*h[0] + w4[1]*h[1] + w4[2]*h[2] + bb4;

        __shared__ float souts[2][KK];
        souts[s][k] = out;
        __syncthreads();

        if (tid < KK) {
            float lo = souts[0][tid], up = souts[1][tid];
            float ssum = lo + up;
            float sg = (ssum > 0.0f) ? -1.0f : ((ssum < 0.0f) ? 1.0f : 0.0f);
            float su = 1.0f / (1.0f + expf(-sg * up));
            float sl = 1.0f / (1.0f + expf(-sg * lo));
            float lik = fmaxf(fabsf(su - sl), LIK_BOUND);
            g_tab[c * KK + tid] = make_float2(cb[tid], lik);
        }
    }

    // PDL: allow the dependent (quant) kernel to begin launching
    asm volatile("griddepcontrol.launch_dependents;");
}

// grid = CC * 8 blocks; block b handles channel c = b % CC, planes n = (b/CC)*2 + {0,1}.
// 256 threads x 2 planes x 16 elements = 8192 elements per block.
__global__ void __launch_bounds__(256) quant_lik_kernel(
    const float4* __restrict__ x4,
    float4* __restrict__ y4,
    float4* __restrict__ l4)
{
    __shared__ float4 sbin[NBINS];   // {y_lo, lik_lo (neg = flag), y_hi, lik_hi}
    __shared__ float2 stab[KK];
    __shared__ float  smid[KK];

    int tid = threadIdx.x;
    int c = blockIdx.x % CC;
    int g = blockIdx.x / CC;          // plane group 0..7

    // base of first plane, in float4 units
    long base = ((long)(g * PLANES_PER_BLOCK) * CC + c) * 1024 + tid;
    const long PSTRIDE = (long)CC * 1024;

    // Prefetch plane 0 before waiting on the producer kernel (PDL overlap)
    float4 xv[4];
    #pragma unroll
    for (int v = 0; v < 4; v++) xv[v] = __ldcs(&x4[base + v * 256]);

    asm volatile("griddepcontrol.wait;" ::: "memory");

    if (tid < KK) {
        stab[tid] = g_tab[c * KK + tid];
        smid[tid] = g_mid[tid];
    }
    __syncthreads();

    // Build the fused per-channel bin table (8 entries/thread)
    #pragma unroll
    for (int r = 0; r < 8; r++) {
        int bin = tid + r * 256;
        unsigned d = g_desc[bin];
        int klo = (int)(d & 0xFFu);
        int n   = (int)(d >> 8);
        float2 lo2 = stab[klo];
        float2 hi2 = stab[min(klo + (n > 0 ? 1 : 0), KK - 1)];
        float flag_or_lik = (n >= 2) ? -(float)(klo + 1) : lo2.y;
        sbin[bin] = make_float4(lo2.x, flag_or_lik, hi2.x, hi2.y);
    }
    __syncthreads();

    #pragma unroll
    for (int p = 0; p < PLANES_PER_BLOCK; p++) {
        long pbase = base + p * PSTRIDE;
        if (p > 0) {
            #pragma unroll
            for (int v = 0; v < 4; v++) xv[v] = __ldcs(&x4[pbase + v * 256]);
        }
        const float* xs = (const float*)xv;

        #pragma unroll
        for (int v = 0; v < 4; v++) {
            float ys[4], ls[4];
            #pragma unroll
            for (int j = 0; j < 4; j++) {
                float xx = xs[v * 4 + j];
                float xc = fminf(fmaxf(xx, -XCLAMP), XCLAMP);
                int bin = __float_as_int(fmaf(xc, BIN_INV, BIN_MAGIC)) & 0x7FF;
                float4 e = sbin[bin];
                if (e.y < 0.0f) {
                    // rare (~0.4%): >=2 midpoints in the window; exact scan
                    int k = (int)(-e.y) - 1;
                    while (smid[k] < xx) k++;   // smid[63] = +INF bounds
                    float2 gg = stab[k];
                    ys[j] = gg.x; ls[j] = gg.y;
                } else {
                    float thr = 0.5f * (e.x + e.z);   // == smid[klo] bit-exactly
                    bool hi = thr < xx;
                    ys[j] = hi ? e.z : e.x;
                    ls[j] = hi ? e.w : e.y;
                }
            }
            long i = pbase + v * 256;
            __stcs(&y4[i], make_float4(ys[0], ys[1], ys[2], ys[3]));
            __stcs(&l4[i], make_float4(ls[0], ls[1], ls[2], ls[3]));
        }
    }
}

extern "C" void kernel_launch(void* const* d_in, const int* in_sizes, int n_in,
                              void* d_out, int out_size)
{
    // metadata order: x, codebook, m0, b0, f0, m1, b1, f1, m2, b2, f2, m3, b3, f3, m4, b4
    const float* x  = (const float*)d_in[0];
    const float* cb = (const float*)d_in[1];
    const float* m0 = (const float*)d_in[2];
    const float* b0 = (const float*)d_in[3];
    const float* f0 = (const float*)d_in[4];
    const float* m1 = (const float*)d_in[5];
    const float* b1 = (const float*)d_in[6];
    const float* f1 = (const float*)d_in[7];
    const float* m2 = (const float*)d_in[8];
    const float* b2 = (const float*)d_in[9];
    const float* f2 = (const float*)d_in[10];
    const float* m3 = (const float*)d_in[11];
    const float* b3 = (const float*)d_in[12];
    const float* f3 = (const float*)d_in[13];
    const float* m4 = (const float*)d_in[14];
    const float* b4 = (const float*)d_in[15];

    long total = (long)in_sizes[0];        // 16*192*64*64 = 12582912
    int nplanes = (int)(total / 4096);     // 3072
    int nblocks = nplanes / PLANES_PER_BLOCK;  // 1536

    float* yhat = (float*)d_out;
    float* lik  = (float*)d_out + total;

    build_lut_kernel<<<CC + NBINS / 256, 128>>>(
        cb, m0, m1, m2, m3, m4, b0, b1, b2, b3, b4, f0, f1, f2, f3);

    // Launch quant with Programmatic Stream Serialization (PDL overlap)
    cudaLaunchConfig_t cfg = {};
    cfg.gridDim = dim3((unsigned)nblocks);
    cfg.blockDim = dim3(256);
    cfg.dynamicSmemBytes = 0;
    cfg.stream = 0;
    cudaLaunchAttribute attrs[1];
    attrs[0].id = cudaLaunchAttributeProgrammaticStreamSerialization;
    attrs[0].val.programmaticStreamSerializationAllowed = 1;
    cfg.attrs = attrs;
    cfg.numAttrs = 1;
    cudaLaunchKernelEx(&cfg, quant_lik_kernel,
                       (const float4*)x, (float4*)yhat, (float4*)lik);
}